// round 15
// baseline (speedup 1.0000x reference)
#include <cuda_runtime.h>
#include <cuda_bf16.h>
#include <math.h>
#include <stdint.h>

#define N_NODES 50000
#define E_EDGES 800000
#define N_ET    (E_EDGES + N_NODES)   // 850000 edges incl. self loops
#define EDIM    101
#define LP      104                   // padded loop_attr pitch
#define HC      128
#define NH      4

// ---- edge mma config: pair-local 16-edge blocks, permuted LDS.64 layout ----
#define NBLK    ((N_ET + 15) / 16)    // 53125
#define NKS     7                     // k-steps of 16 (K padded to 112)
#define PW      72                    // A/B row pitch in words (== 8 mod 32)
#define EEP     132                   // ee row pitch (floats)

// fragment-pair permutation within each 8-word group
#define PERMQ(kq) (((kq) & ~7) | ((((kq) & 3)) << 1) | (((kq) & 7) >> 2))

// edge smem offsets (bytes)
#define SM_SS    0
#define SM_DS    512
#define SM_BHI   1024                 // 128*72*4 = 36864
#define SM_BLO   (SM_BHI + 36864)
#define SM_AHI   (SM_BLO + 36864)
#define SM_ALO   (SM_AHI + 36864)
#define SM_EE    (SM_ALO + 36864)     // 8*16*132*4 = 67584
#define SM_TOTAL (SM_EE + 67584)      // 216064

// gemm smem (single): pitch 68 words
#define GPW      68
#define GSM_BHI  0
#define GSM_BLO  (128*GPW*4)
#define GSM_AHI  (2*128*GPW*4)
#define GSM_ALO  (3*128*GPW*4)
#define GSM_TOTAL (4*128*GPW*4)       // 139264

// dual gemm smem: B1h,B1l,B2h,B2l,Ah,Al
#define DSM_B1H  0
#define DSM_B1L  34816
#define DSM_B2H  69632
#define DSM_B2L  104448
#define DSM_AH   139264
#define DSM_AL   174080
#define DSM_TOTAL 208896

// ------------------------------ scratch ------------------------------------
__device__ int      g_is64;
__device__ int      g_eidx[2 * E_EDGES];
__device__ float    g_loop[(size_t)N_NODES * LP];
__device__ float    g_xl  [(size_t)N_NODES * HC];
__device__ float    g_xr  [(size_t)N_NODES * HC];
__device__ float    g_h   [(size_t)N_NODES * HC];
__device__ float    g_t1  [(size_t)N_NODES * HC];
__device__ float    g_den [(size_t)N_NODES * NH];
__device__ float    g_agg [(size_t)N_NODES * HC];
// preconverted weights: 7 slots (c1_Wl, c1_Wr, c1_We, c2_Wl, c2_Wr, c2_We, W1)
__device__ uint32_t g_wh[7][128 * 64];
__device__ uint32_t g_wl[7][128 * 64];
// CSR scratch
__device__ int      g_deg [N_NODES];
__device__ int      g_off [N_NODES + 1];
__device__ int      g_pos [N_NODES];
__device__ int      g_eid [E_EDGES];
__device__ int      g_bsum[64];
__device__ int      g_bpre[64];

// ------------------------------ helpers ------------------------------------
__device__ __forceinline__ void redAdd4(float* p, float4 v) {
    asm volatile("red.global.add.v4.f32 [%0], {%1,%2,%3,%4};"
                 :: "l"(p), "f"(v.x), "f"(v.y), "f"(v.z), "f"(v.w) : "memory");
}

// truncation-based bf16 hi/lo split of a float pair (residual 2^-16 after 3-term)
__device__ __forceinline__ void split_trunc(float v0, float v1,
                                            uint32_t& hi, uint32_t& lo) {
    uint32_t u0 = __float_as_uint(v0), u1 = __float_as_uint(v1);
    hi = __byte_perm(u0, u1, 0x7632);
    float r0 = v0 - __uint_as_float(u0 & 0xFFFF0000u);
    float r1 = v1 - __uint_as_float(u1 & 0xFFFF0000u);
    lo = __byte_perm(__float_as_uint(r0), __float_as_uint(r1), 0x7632);
}

// HMMA m16n8k16 bf16 (baseline PTX, sm_80+)
__device__ __forceinline__ void mma_bf16(float* d,
                                         uint32_t a0, uint32_t a1, uint32_t a2, uint32_t a3,
                                         uint32_t b0, uint32_t b1) {
    asm volatile("mma.sync.aligned.m16n8k16.row.col.f32.bf16.bf16.f32 "
                 "{%0,%1,%2,%3}, {%4,%5,%6,%7}, {%8,%9}, {%0,%1,%2,%3};"
                 : "+f"(d[0]), "+f"(d[1]), "+f"(d[2]), "+f"(d[3])
                 : "r"(a0), "r"(a1), "r"(a2), "r"(a3), "r"(b0), "r"(b1));
}

#define PAIR_BAR(pair) asm volatile("bar.sync %0, %1;" :: "r"((pair) + 1), "r"(64) : "memory")

// ------------------------------ index dtype hedge ---------------------------
__global__ void detect_idx(const void* ei) {
    const int* p = (const int*)ei;
    int all0 = 1;
    for (int i = 1; i < 64; i += 2) if (p[i] != 0) all0 = 0;
    g_is64 = all0;
}

__global__ void conv_idx(const void* ei) {
    int i = blockIdx.x * blockDim.x + threadIdx.x;
    if (i < N_NODES) g_deg[i] = 0;
    if (i >= 2 * E_EDGES) return;
    int v;
    if (g_is64) v = (int)((const long long*)ei)[i];
    else        v = ((const int*)ei)[i];
    g_eidx[i] = v;
}

// ------------------------------ CSR loop-attr mean --------------------------
__global__ void deg_count(const int* __restrict__ dst) {
    int e = blockIdx.x * blockDim.x + threadIdx.x;
    if (e >= E_EDGES) return;
    atomicAdd(&g_deg[dst[e]], 1);
}

__global__ void scan_part() {
    __shared__ int red[32];
    int t = threadIdx.x;
    int lane = t & 31, wid = t >> 5;
    int n = blockIdx.x * 1024 + t;
    int v = (n < N_NODES) ? g_deg[n] : 0;
#pragma unroll
    for (int off = 16; off > 0; off >>= 1)
        v += __shfl_down_sync(0xffffffffu, v, off);
    if (lane == 0) red[wid] = v;
    __syncthreads();
    if (wid == 0) {
        int s = red[lane];
#pragma unroll
        for (int off = 16; off > 0; off >>= 1)
            s += __shfl_down_sync(0xffffffffu, s, off);
        if (lane == 0) g_bsum[blockIdx.x] = s;
    }
}

__global__ void scan_top(int nblocks) {
    __shared__ int s[64];
    int t = threadIdx.x;
    int v = (t < nblocks) ? g_bsum[t] : 0;
    s[t] = v;
    __syncthreads();
#pragma unroll
    for (int off = 1; off < 64; off <<= 1) {
        int u = (t >= off) ? s[t - off] : 0;
        __syncthreads();
        s[t] += u;
        __syncthreads();
    }
    g_bpre[t] = s[t] - v;
}

__global__ void scan_fin() {
    __shared__ int wsum[32];
    int t = threadIdx.x;
    int lane = t & 31, wid = t >> 5;
    int n = blockIdx.x * 1024 + t;
    int v = (n < N_NODES) ? g_deg[n] : 0;
    int x = v;
#pragma unroll
    for (int off = 1; off < 32; off <<= 1) {
        int u = __shfl_up_sync(0xffffffffu, x, off);
        if (lane >= off) x += u;
    }
    if (lane == 31) wsum[wid] = x;
    __syncthreads();
    if (wid == 0) {
        int y = wsum[lane];
#pragma unroll
        for (int off = 1; off < 32; off <<= 1) {
            int u = __shfl_up_sync(0xffffffffu, y, off);
            if (lane >= off) y += u;
        }
        wsum[lane] = y;
    }
    __syncthreads();
    int bpre = (wid > 0) ? wsum[wid - 1] : 0;
    int excl = x - v + bpre + g_bpre[blockIdx.x];
    if (n < N_NODES) {
        g_off[n] = excl;
        g_pos[n] = excl;
    }
    if (blockIdx.x == 0 && t == 0) g_off[N_NODES] = E_EDGES;
}

__global__ void scatter_eid(const int* __restrict__ dst) {
    int e = blockIdx.x * blockDim.x + threadIdx.x;
    if (e >= E_EDGES) return;
    int p = atomicAdd(&g_pos[dst[e]], 1);
    g_eid[p] = e;
}

// warp per node, unrolled x2 (two row fetches in flight)
__global__ void loop_mean(const float* __restrict__ ea) {
    int n = blockIdx.x * 8 + (threadIdx.x >> 5);
    if (n >= N_NODES) return;
    int lane = threadIdx.x & 31;
    int c0 = lane << 2;
    int o0 = g_off[n], o1 = g_off[n + 1];
    float a0 = 0.f, a1 = 0.f, a2 = 0.f, a3 = 0.f;
    float b0 = 0.f, b1 = 0.f, b2 = 0.f, b3 = 0.f;
    int j = o0;
    for (; j + 1 < o1; j += 2) {
        const float* p0 = ea + (size_t)g_eid[j]     * EDIM;
        const float* p1 = ea + (size_t)g_eid[j + 1] * EDIM;
        if (c0 < EDIM)     { a0 += p0[c0];     b0 += p1[c0]; }
        if (c0 + 1 < EDIM) { a1 += p0[c0 + 1]; b1 += p1[c0 + 1]; }
        if (c0 + 2 < EDIM) { a2 += p0[c0 + 2]; b2 += p1[c0 + 2]; }
        if (c0 + 3 < EDIM) { a3 += p0[c0 + 3]; b3 += p1[c0 + 3]; }
    }
    if (j < o1) {
        const float* p0 = ea + (size_t)g_eid[j] * EDIM;
        if (c0 < EDIM)     a0 += p0[c0];
        if (c0 + 1 < EDIM) a1 += p0[c0 + 1];
        if (c0 + 2 < EDIM) a2 += p0[c0 + 2];
        if (c0 + 3 < EDIM) a3 += p0[c0 + 3];
    }
    float inv = 1.f / (float)max(o1 - o0, 1);
    float* out = g_loop + (size_t)n * LP;
    if (c0 < EDIM)     out[c0]     = (a0 + b0) * inv;
    if (c0 + 1 < EDIM) out[c0 + 1] = (a1 + b1) * inv;
    if (c0 + 2 < EDIM) out[c0 + 2] = (a2 + b2) * inv;
    if (c0 + 3 < EDIM) out[c0 + 3] = (a3 + b3) * inv;
}

// ---- batched weight preconversion: all 7 weights -> hi/lo slots -----------
__global__ void convW7(const float* W0, const float* W1_, const float* W2_,
                       const float* W3_, const float* W4_, const float* W5_,
                       const float* W6_) {
    int gid = blockIdx.x * 256 + threadIdx.x;
    int slot = gid >> 13;              // 8192 entries per slot
    int idx = gid & 8191;
    if (slot >= 7) return;
    const float* W;
    int kmax;
    switch (slot) {
        case 0: W = W0;  kmax = 128;  break;
        case 1: W = W1_; kmax = 128;  break;
        case 2: W = W2_; kmax = EDIM; break;
        case 3: W = W3_; kmax = 128;  break;
        case 4: W = W4_; kmax = 128;  break;
        case 5: W = W5_; kmax = EDIM; break;
        default: W = W6_; kmax = 128; break;
    }
    int c = idx >> 6, kq = idx & 63;
    int k = kq * 2;
    float v0 = (k     < kmax) ? W[(size_t)k * 128 + c]       : 0.f;
    float v1 = (k + 1 < kmax) ? W[(size_t)(k + 1) * 128 + c] : 0.f;
    uint32_t h, l;
    split_trunc(v0, v1, h, l);
    g_wh[slot][idx] = h;
    g_wl[slot][idx] = l;
}

// ------------- persistent HMMA node GEMM (single W) -------------------------
__global__ __launch_bounds__(512, 1)
void gemm_mma(const float* __restrict__ A, const float* __restrict__ bias,
              float* __restrict__ C, int M, int relu,
              const uint32_t* __restrict__ wh, const uint32_t* __restrict__ wl) {
    extern __shared__ __align__(16) char sm[];
    uint32_t* Bh = (uint32_t*)(sm + GSM_BHI);
    uint32_t* Bl = (uint32_t*)(sm + GSM_BLO);
    uint32_t* Ah = (uint32_t*)(sm + GSM_AHI);
    uint32_t* Al = (uint32_t*)(sm + GSM_ALO);

    int t = threadIdx.x;
    int lane = t & 31;
    int w = t >> 5;
    int mb = w >> 1, half = w & 1;
    int r0 = lane >> 2, kp = lane & 3;

#pragma unroll
    for (int i = 0; i < 16; i++) {
        int idx = t + i * 512;
        int c = idx >> 6, kq = idx & 63;
        Bh[c * GPW + kq] = wh[idx];
        Bl[c * GPW + kq] = wl[idx];
    }

    int r = t >> 2;
    int kq0 = (t & 3) << 4;
    int cb = (half << 6) + (kp << 1);

    for (int m0 = blockIdx.x << 7; m0 < M; m0 += gridDim.x << 7) {
        __syncthreads();   // prev tile MMA reads of A done (covers B on iter 0)
        {
            int m = m0 + r;
            const float* ap = A + (size_t)m * 128 + (kq0 << 1);
            uint32_t* ah = Ah + r * GPW + kq0;
            uint32_t* al = Al + r * GPW + kq0;
            bool ok = (m < M);
#pragma unroll
            for (int i = 0; i < 16; i++) {
                float v0 = ok ? ap[2*i]     : 0.f;
                float v1 = ok ? ap[2*i + 1] : 0.f;
                uint32_t h, l;
                split_trunc(v0, v1, h, l);
                ah[i] = h;
                al[i] = l;
            }
        }
        __syncthreads();

        float acc[8][4];
#pragma unroll
        for (int nb = 0; nb < 8; nb++)
#pragma unroll
            for (int j = 0; j < 4; j++) acc[nb][j] = 0.f;

        const uint32_t* Awh = Ah + (mb << 4) * GPW;
        const uint32_t* Awl = Al + (mb << 4) * GPW;
        const uint32_t* Bwh = Bh + (half << 6) * GPW;
        const uint32_t* Bwl = Bl + (half << 6) * GPW;

#pragma unroll
        for (int ks = 0; ks < 8; ks++) {
            int abase = r0 * GPW + ks * 8 + kp;
            uint32_t ah0 = Awh[abase],     ah1 = Awh[abase + 8 * GPW];
            uint32_t ah2 = Awh[abase + 4], ah3 = Awh[abase + 8 * GPW + 4];
            uint32_t al0 = Awl[abase],     al1 = Awl[abase + 8 * GPW];
            uint32_t al2 = Awl[abase + 4], al3 = Awl[abase + 8 * GPW + 4];
#pragma unroll
            for (int nb = 0; nb < 8; nb++) {
                int bbase = ((nb << 3) + r0) * GPW + ks * 8 + kp;
                uint32_t bh0 = Bwh[bbase], bh1 = Bwh[bbase + 4];
                uint32_t bl0 = Bwl[bbase], bl1 = Bwl[bbase + 4];
                mma_bf16(acc[nb], ah0, ah1, ah2, ah3, bh0, bh1);
                mma_bf16(acc[nb], ah0, ah1, ah2, ah3, bl0, bl1);
                mma_bf16(acc[nb], al0, al1, al2, al3, bh0, bh1);
            }
        }

        int mA = m0 + (mb << 4) + r0;
        int mB = mA + 8;
#pragma unroll
        for (int nb = 0; nb < 8; nb++) {
            int c0 = cb + (nb << 3);
            float2 bv = *(const float2*)(bias + c0);
            float o0 = acc[nb][0] + bv.x, o1 = acc[nb][1] + bv.y;
            float o2 = acc[nb][2] + bv.x, o3 = acc[nb][3] + bv.y;
            if (relu) {
                o0 = fmaxf(o0, 0.f); o1 = fmaxf(o1, 0.f);
                o2 = fmaxf(o2, 0.f); o3 = fmaxf(o3, 0.f);
            }
            if (mA < M) *(float2*)(C + (size_t)mA * 128 + c0) = make_float2(o0, o1);
            if (mB < M) *(float2*)(C + (size_t)mB * 128 + c0) = make_float2(o2, o3);
        }
    }
}

// ------------- persistent dual HMMA node GEMM: C1 = A@W1+b1, C2 = A@W2+b2 ---
__global__ __launch_bounds__(512, 1)
void gemm_dual(const float* __restrict__ A,
               const float* __restrict__ b1, const float* __restrict__ b2,
               float* __restrict__ C1, float* __restrict__ C2, int M,
               const uint32_t* __restrict__ w1h, const uint32_t* __restrict__ w1l,
               const uint32_t* __restrict__ w2h, const uint32_t* __restrict__ w2l) {
    extern __shared__ __align__(16) char sm[];
    uint32_t* B1h = (uint32_t*)(sm + DSM_B1H);
    uint32_t* B1l = (uint32_t*)(sm + DSM_B1L);
    uint32_t* B2h = (uint32_t*)(sm + DSM_B2H);
    uint32_t* B2l = (uint32_t*)(sm + DSM_B2L);
    uint32_t* Ah  = (uint32_t*)(sm + DSM_AH);
    uint32_t* Al  = (uint32_t*)(sm + DSM_AL);

    int t = threadIdx.x;
    int lane = t & 31;
    int w = t >> 5;
    int mb = w >> 1, half = w & 1;
    int r0 = lane >> 2, kp = lane & 3;

#pragma unroll
    for (int i = 0; i < 16; i++) {
        int idx = t + i * 512;
        int c = idx >> 6, kq = idx & 63;
        B1h[c * GPW + kq] = w1h[idx];
        B1l[c * GPW + kq] = w1l[idx];
        B2h[c * GPW + kq] = w2h[idx];
        B2l[c * GPW + kq] = w2l[idx];
    }

    int r = t >> 2;
    int kq0 = (t & 3) << 4;
    int cb = (half << 6) + (kp << 1);

    for (int m0 = blockIdx.x << 7; m0 < M; m0 += gridDim.x << 7) {
        __syncthreads();
        {
            int m = m0 + r;
            const float* ap = A + (size_t)m * 128 + (kq0 << 1);
            uint32_t* ah = Ah + r * GPW + kq0;
            uint32_t* al = Al + r * GPW + kq0;
            bool ok = (m < M);
#pragma unroll
            for (int i = 0; i < 16; i++) {
                float v0 = ok ? ap[2*i]     : 0.f;
                float v1 = ok ? ap[2*i + 1] : 0.f;
                uint32_t h, l;
                split_trunc(v0, v1, h, l);
                ah[i] = h;
                al[i] = l;
            }
        }
        __syncthreads();

        const uint32_t* Awh = Ah + (mb << 4) * GPW;
        const uint32_t* Awl = Al + (mb << 4) * GPW;
        int mA = m0 + (mb << 4) + r0;
        int mB = mA + 8;

#pragma unroll
        for (int pass = 0; pass < 2; pass++) {
            const uint32_t* Bwh = (pass ? B2h : B1h) + (half << 6) * GPW;
            const uint32_t* Bwl = (pass ? B2l : B1l) + (half << 6) * GPW;
            const float* bias = pass ? b2 : b1;
            float* C = pass ? C2 : C1;

            float acc[8][4];
#pragma unroll
            for (int nb = 0; nb < 8; nb++)
#pragma unroll
                for (int j = 0; j < 4; j++) acc[nb][j] = 0.f;

#pragma unroll
            for (int ks = 0; ks < 8; ks++) {
                int abase = r0 * GPW + ks * 8 + kp;
                uint32_t ah0 = Awh[abase],     ah1 = Awh[abase + 8 * GPW];
                uint32_t ah2 = Awh[abase + 4], ah3 = Awh[abase + 8 * GPW + 4];
                uint32_t al0 = Awl[abase],     al1 = Awl[abase + 8 * GPW];
                uint32_t al2 = Awl[abase + 4], al3 = Awl[abase + 8 * GPW + 4];
#pragma unroll
                for (int nb = 0; nb < 8; nb++) {
                    int bbase = ((nb << 3) + r0) * GPW + ks * 8 + kp;
                    uint32_t bh0 = Bwh[bbase], bh1 = Bwh[bbase + 4];
                    uint32_t bl0 = Bwl[bbase], bl1 = Bwl[bbase + 4];
                    mma_bf16(acc[nb], ah0, ah1, ah2, ah3, bh0, bh1);
                    mma_bf16(acc[nb], ah0, ah1, ah2, ah3, bl0, bl1);
                    mma_bf16(acc[nb], al0, al1, al2, al3, bh0, bh1);
                }
            }

#pragma unroll
            for (int nb = 0; nb < 8; nb++) {
                int c0 = cb + (nb << 3);
                float2 bv = *(const float2*)(bias + c0);
                float o0 = acc[nb][0] + bv.x, o1 = acc[nb][1] + bv.y;
                float o2 = acc[nb][2] + bv.x, o3 = acc[nb][3] + bv.y;
                if (mA < M) *(float2*)(C + (size_t)mA * 128 + c0) = make_float2(o0, o1);
                if (mB < M) *(float2*)(C + (size_t)mB * 128 + c0) = make_float2(o2, o3);
            }
        }
    }
}

// ==== HMMA fused edge kernel: pair-local pipelines, LDS.64 permuted layout,
//      epilogue batch-0 gathers hoisted above the ee barrier ================
__device__ __forceinline__ void prefetch_attrs(size_t e, int kbase, float* pf,
                                               const float* __restrict__ eattr) {
    bool ok = (e < (size_t)N_ET);
    const float* bp = (e < E_EDGES) ? (eattr + e * EDIM)
                    : (g_loop + (ok ? (e - E_EDGES) : 0) * (size_t)LP);
#pragma unroll
    for (int i = 0; i < 28; i++) {
        int k = kbase + i;
        pf[i] = (ok && k < EDIM) ? bp[k] : 0.f;
    }
}

__global__ __launch_bounds__(512, 1)
void edge_mma(const int* __restrict__ src, const int* __restrict__ dst,
              const float* __restrict__ eattr, const float* __restrict__ att,
              const uint32_t* __restrict__ wh, const uint32_t* __restrict__ wl) {
    extern __shared__ __align__(16) char sm[];
    int*      ssS = (int*)(sm + SM_SS);
    int*      dsS = (int*)(sm + SM_DS);
    uint32_t* Bhi = (uint32_t*)(sm + SM_BHI);
    uint32_t* Blo = (uint32_t*)(sm + SM_BLO);
    uint32_t* Ahi = (uint32_t*)(sm + SM_AHI);
    uint32_t* Alo = (uint32_t*)(sm + SM_ALO);
    float*    ee  = (float*)(sm + SM_EE);

    int t = threadIdx.x;
    int lane = t & 31;
    int w = t >> 5;
    int pair = w >> 1, half = w & 1;
    int r0 = lane >> 2, kp = lane & 3;
    int head = lane >> 3;
    int u = t & 63;

    // copy preconverted We into permuted smem (kq -> PERMQ(kq), pitch 72)
    for (int i = t; i < 128 * 56; i += 512) {
        int c = i / 56, kq = i - c * 56;
        int pq = PERMQ(kq);
        Bhi[c * PW + pq] = wh[(c << 6) + kq];
        Blo[c * PW + pq] = wl[(c << 6) + kq];
    }
    float4 av = *(const float4*)(att + (lane << 2));
    __syncthreads();

    uint32_t* pAh = Ahi + pair * (16 * PW);
    uint32_t* pAl = Alo + pair * (16 * PW);
    float*    pee = ee  + pair * (16 * EEP);
    float2*   pee2 = (float2*)pee;
    int*      pss = ssS + (pair << 4);
    int*      pds = dsS + (pair << 4);

    const uint32_t* Bwh = Bhi + (half << 6) * PW;
    const uint32_t* Bwl = Blo + (half << 6) * PW;

    int e_st = u >> 2;
    int kq0 = (u & 3) * 14;
    int kbase = kq0 * 2;
    int stride = gridDim.x * 8;
    int blk0 = blockIdx.x * 8 + pair;

    float pf[28];
    prefetch_attrs((size_t)blk0 * 16 + e_st, kbase, pf, eattr);

    for (int blk = blk0; blk < NBLK; blk += stride) {
        size_t e0 = (size_t)blk * 16;

        if (u < 16) {
            size_t e = e0 + u;
            int s = 0, d = 0;
            if (e < (size_t)N_ET) {
                if (e < E_EDGES) { s = src[e]; d = dst[e]; }
                else             { s = d = (int)(e - E_EDGES); }
            }
            pss[u] = s; pds[u] = d;
        }
        {
            uint32_t* ah = pAh + e_st * PW;
            uint32_t* al = pAl + e_st * PW;
#pragma unroll
            for (int i = 0; i < 14; i++) {
                int kq = kq0 + i;
                int pq = PERMQ(kq);
                uint32_t h, l;
                split_trunc(pf[2*i], pf[2*i + 1], h, l);
                ah[pq] = h;
                al[pq] = l;
            }
        }
        if (blk + stride < NBLK)
            prefetch_attrs((size_t)(blk + stride) * 16 + e_st, kbase, pf, eattr);

        PAIR_BAR(pair);

        float acc[8][4];
#pragma unroll
        for (int nb = 0; nb < 8; nb++)
#pragma unroll
            for (int j = 0; j < 4; j++) acc[nb][j] = 0.f;

#pragma unroll
        for (int ks = 0; ks < NKS; ks++) {
            int ab = r0 * PW + ks * 8 + (kp << 1);
            uint2 aH0 = *(const uint2*)(pAh + ab);
            uint2 aH1 = *(const uint2*)(pAh + ab + 8 * PW);
            uint2 aL0 = *(const uint2*)(pAl + ab);
            uint2 aL1 = *(const uint2*)(pAl + ab + 8 * PW);
#pragma unroll
            for (int nb = 0; nb < 8; nb++) {
                int bb = ((nb << 3) + r0) * PW + ks * 8 + (kp << 1);
                uint2 bH = *(const uint2*)(Bwh + bb);
                uint2 bL = *(const uint2*)(Bwl + bb);
                mma_bf16(acc[nb], aH0.x, aH1.x, aH0.y, aH1.y, bH.x, bH.y);
                mma_bf16(acc[nb], aH0.x, aH1.x, aH0.y, aH1.y, bL.x, bL.y);
                mma_bf16(acc[nb], aL0.x, aL1.x, aL0.y, aL1.y, bH.x, bH.y);
            }
        }

#pragma unroll
        for (int nb = 0; nb < 8; nb++) {
            int col2 = (half << 5) + (nb << 2) + kp;
            pee2[r0 * (EEP / 2) + col2]       = make_float2(acc[nb][0], acc[nb][1]);
            pee2[(r0 + 8) * (EEP / 2) + col2] = make_float2(acc[nb][2], acc[nb][3]);
        }

        // snapshot indices BEFORE the bar (next stage overwrites pss)
        int sreg[8], dreg[8];
        bool vv[8];
#pragma unroll
        for (int i = 0; i < 8; i++) {
            int el = (half << 3) + i;
            size_t e = e0 + el;
            vv[i] = (e < (size_t)N_ET);
            sreg[i] = vv[i] ? pss[el] : 0;
            dreg[i] = vv[i] ? pds[el] : 0;
        }

        // HOIST: batch-0 gathers (depend only on sreg/dreg; L2 latency hides
        // under the barrier wait + partner's ee stores)
        float4 xlv0[4], xrv0[4];
#pragma unroll
        for (int i = 0; i < 4; i++) {
            xlv0[i] = *(const float4*)(g_xl + (size_t)sreg[i] * HC + (lane << 2));
            xrv0[i] = *(const float4*)(g_xr + (size_t)dreg[i] * HC + (lane << 2));
        }

        PAIR_BAR(pair);               // ee complete (both halves)

        // ---- epilogue batch 0 (preloaded gathers) ----
#pragma unroll
        for (int i = 0; i < 4; i++) {
            int el = (half << 3) + i;
            float4 eev = *(const float4*)(pee + el * EEP + (lane << 2));
            float z0 = eev.x + xlv0[i].x + xrv0[i].x;
            float z1 = eev.y + xlv0[i].y + xrv0[i].y;
            float z2 = eev.z + xlv0[i].z + xrv0[i].z;
            float z3 = eev.w + xlv0[i].w + xrv0[i].w;
            z0 = (z0 > 0.f) ? z0 : 0.2f * z0;
            z1 = (z1 > 0.f) ? z1 : 0.2f * z1;
            z2 = (z2 > 0.f) ? z2 : 0.2f * z2;
            z3 = (z3 > 0.f) ? z3 : 0.2f * z3;
            float part = z0 * av.x + z1 * av.y + z2 * av.z + z3 * av.w;
            part += __shfl_xor_sync(0xffffffffu, part, 1);
            part += __shfl_xor_sync(0xffffffffu, part, 2);
            part += __shfl_xor_sync(0xffffffffu, part, 4);
            float ex = __expf(part);
            if (vv[i]) {
                if ((lane & 7) == 0)
                    atomicAdd(&g_den[(size_t)dreg[i] * NH + head], ex);
                redAdd4(g_agg + (size_t)dreg[i] * HC + (lane << 2),
                        make_float4(ex * xlv0[i].x, ex * xlv0[i].y,
                                    ex * xlv0[i].z, ex * xlv0[i].w));
            }
        }

        // ---- epilogue batch 1 ----
        {
            float4 xlv[4], xrv[4];
#pragma unroll
            for (int i = 0; i < 4; i++) {
                int j = 4 + i;
                xlv[i] = *(const float4*)(g_xl + (size_t)sreg[j] * HC + (lane << 2));
                xrv[i] = *(const float4*)(g_xr + (size_t)dreg[j] * HC + (lane << 2));
            }
#pragma unroll
            for (int i = 0; i < 4; i++) {
                int j = 4 + i;
                int el = (half << 3) + j;
                float4 eev = *(const float4*)(pee + el * EEP + (lane << 2));
                float z0 = eev.x + xlv[i].x + xrv[i].x;
                float z1 = eev.y + xlv[i].y + xrv[i].y;
                float z2 = eev.z + xlv[i].z + xrv[i].z;
                float z3 = eev.w + xlv[i].w + xrv[i].w;
                z0 = (z0 > 0.f) ? z0 : 0.2f * z0;
                z1 = (z1 > 0.f) ? z1 : 0.2f * z1;
                z2 = (z2 > 0.f) ? z2 : 0.2f * z2;
                z3 = (z3 > 0.f) ? z3 : 0.2f * z3;
                float part = z0 * av.x + z1 * av.y + z2 * av.z + z3 * av.w;
                part += __shfl_xor_sync(0xffffffffu, part, 1);
                part += __shfl_xor_sync(0xffffffffu, part, 2);
                part += __shfl_xor_sync(0xffffffffu, part, 4);
                float ex = __expf(part);
                if (vv[j]) {
                    if ((lane & 7) == 0)
                        atomicAdd(&g_den[(size_t)dreg[j] * NH + head], ex);
                    redAdd4(g_agg + (size_t)dreg[j] * HC + (lane << 2),
                            make_float4(ex * xlv[i].x, ex * xlv[i].y,
                                        ex * xlv[i].z, ex * xlv[i].w));
                }
            }
        }
    }
}

// ---- h = relu(agg/(den+eps) + bias); then zero agg/den for next layer/call -
__global__ void node_finalize(const float* __restrict__ bias, float* __restrict__ out) {
    size_t i = (size_t)blockIdx.x * blockDim.x + threadIdx.x;   // exact grid
    int n = (int)(i >> 7), c = (int)(i & 127);
    float den = g_den[(size_t)n * NH + (c >> 5)];
    float agg = g_agg[i];
    __syncthreads();   // all reads of den in this block done before zeroing
    float v = agg / (den + 1e-16f) + bias[c];
    out[i] = fmaxf(v, 0.f);
    g_agg[i] = 0.f;
    if ((c & 31) == 0) g_den[(size_t)n * NH + (c >> 5)] = 0.f;
}

// --------------------- MLP tail: relu(t1@W2+b2) @ W3 + b3 ------------------
__global__ void mlp_tail(const float* __restrict__ W2, const float* __restrict__ b2,
                         const float* __restrict__ W3, const float* __restrict__ b3,
                         float* __restrict__ out) {
    __shared__ float W2s[128 * 64];
    __shared__ float t1s[16 * 132];
    __shared__ float W3s[64];
    int t = threadIdx.x;
    int n0 = blockIdx.x * 16;
    for (int i = t; i < 128 * 64 / 4; i += 128)
        ((float4*)W2s)[i] = ((const float4*)W2)[i];
    if (t < 64) W3s[t] = W3[t];
    for (int i = t; i < 16 * 128; i += 128) {
        int ln = i >> 7, k = i & 127;
        int n = n0 + ln;
        t1s[ln * 132 + k] = (n < N_NODES) ? g_t1[(size_t)n * 128 + k] : 0.f;
    }
    __syncthreads();
    int ln = t >> 3, jg = t & 7;
    float acc[8] = {0.f, 0.f, 0.f, 0.f, 0.f, 0.f, 0.f, 0.f};
#pragma unroll 4
    for (int k = 0; k < 128; k++) {
        float a = t1s[ln * 132 + k];
        float4 w0 = *(const float4*)(W2s + k * 64 + jg * 8);
        float4 w1 = *(const float4*)(W2s + k * 64 + jg * 8 + 4);
        acc[0] += a * w0.x; acc[1] += a * w0.y; acc[2] += a * w0.z; acc[3] += a * w0.w;
        acc[4] += a * w1.x; acc[5] += a * w1.y; acc[6] += a * w1.z; acc[7] += a * w1.w;
    }
    float part = 0.f;
#pragma unroll
    for (int j = 0; j < 8; j++) {
        float t2 = fmaxf(acc[j] + b2[jg * 8 + j], 0.f);
        part += t2 * W3s[jg * 8 + j];
    }
    part += __shfl_down_sync(0xffffffffu, part, 4, 8);
    part += __shfl_down_sync(0xffffffffu, part, 2, 8);
    part += __shfl_down_sync(0xffffffffu, part, 1, 8);
    int n = n0 + ln;
    if (jg == 0 && n < N_NODES) out[n] = part + b3[0];
}

// ------------------------------ launch -------------------------------------
extern "C" void kernel_launch(void* const* d_in, const int* in_sizes, int n_in,
                              void* d_out, int out_size) {
    const float* x       = (const float*)d_in[0];
    const void*  ei_raw  = d_in[1];
    const float* ea      = (const float*)d_in[2];
    const float* c1_Wl   = (const float*)d_in[3];
    const float* c1_bl   = (const float*)d_in[4];
    const float* c1_Wr   = (const float*)d_in[5];
    const float* c1_br   = (const float*)d_in[6];
    const float* c1_We   = (const float*)d_in[7];
    const float* c1_att  = (const float*)d_in[8];
    const float* c1_bias = (const float*)d_in[9];
    const float* c2_Wl   = (const float*)d_in[10];
    const float* c2_bl   = (const float*)d_in[11];
    const float* c2_Wr   = (const float*)d_in[12];
    const float* c2_br   = (const float*)d_in[13];
    const float* c2_We   = (const float*)d_in[14];
    const float* c2_att  = (const float*)d_in[15];
    const float* c2_bias = (const float*)d_in[16];
    const float* W1      = (const float*)d_in[17];
    const float* b1      = (const float*)d_in[18];
    const float* W2      = (const float*)d_in[19];
    const float* b2      = (const float*)d_in[20];
    const float* W3      = (const float*)d_in[21];
    const float* b3      = (const float*)d_in[22];
    float* out = (float*)d_out;

    float *p_xl, *p_xr, *p_h, *p_t1;
    int *p_eidx;
    uint32_t *p_wh, *p_wl;
    cudaGetSymbolAddress((void**)&p_xl, g_xl);
    cudaGetSymbolAddress((void**)&p_xr, g_xr);
    cudaGetSymbolAddress((void**)&p_h, g_h);
    cudaGetSymbolAddress((void**)&p_t1, g_t1);
    cudaGetSymbolAddress((void**)&p_eidx, g_eidx);
    cudaGetSymbolAddress((void**)&p_wh, g_wh);
    cudaGetSymbolAddress((void**)&p_wl, g_wl);
    const int* src = p_eidx;
    const int* dst = p_eidx + E_EDGES;
#define WH(s) (p_wh + (s) * 8192)
#define WL(s) (p_wl + (s) * 8192)

    cudaFuncSetAttribute(edge_mma,
                         cudaFuncAttributeMaxDynamicSharedMemorySize, SM_TOTAL);
    cudaFuncSetAttribute(gemm_mma,
                         cudaFuncAttributeMaxDynamicSharedMemorySize, GSM_TOTAL);
    cudaFuncSetAttribute(gemm_dual,
                         cudaFuncAttributeMaxDynamicSharedMemorySize, DSM_TOTAL);

    int nsm = 148;
    cudaDeviceGetAttribute(&nsm, cudaDevAttrMultiProcessorCount, 0);

    const int T = 256;
    int nhc_blocks = (int)(((size_t)N_NODES * HC) / T);  // 25000 exact
    int scan_blocks = (N_NODES + 1023) / 1024;           // 49
    int cw7_blocks = (7 * 8192 + 255) / 256;             // 224

    detect_idx<<<1, 1>>>(ei_raw);
    conv_idx<<<(2 * E_EDGES + T - 1) / T, T>>>(ei_raw);

    // all weight conversions up front (one launch)
    convW7<<<cw7_blocks, 256>>>(c1_Wl, c1_Wr, c1_We, c2_Wl, c2_Wr, c2_We, W1);

    // CSR loop-attr mean
    deg_count<<<(E_EDGES + T - 1) / T, T>>>(dst);
    scan_part<<<scan_blocks, 1024>>>();
    scan_top<<<1, 64>>>(scan_blocks);
    scan_fin<<<scan_blocks, 1024>>>();
    scatter_eid<<<(E_EDGES + T - 1) / T, T>>>(dst);
    loop_mean<<<(N_NODES + 7) / 8, T>>>(ea);

    // ---- layer 1 ----
    gemm_dual<<<nsm, 512, DSM_TOTAL>>>(x, c1_bl, c1_br, p_xl, p_xr, N_NODES,
                                       WH(0), WL(0), WH(1), WL(1));
    edge_mma<<<nsm, 512, SM_TOTAL>>>(src, dst, ea, c1_att, WH(2), WL(2));
    node_finalize<<<nhc_blocks, T>>>(c1_bias, p_h);

    // ---- layer 2 ----
    gemm_dual<<<nsm, 512, DSM_TOTAL>>>(p_h, c2_bl, c2_br, p_xl, p_xr, N_NODES,
                                       WH(3), WL(3), WH(4), WL(4));
    edge_mma<<<nsm, 512, SM_TOTAL>>>(src, dst, ea, c2_att, WH(5), WL(5));
    node_finalize<<<nhc_blocks, T>>>(c2_bias, p_h);

    // ---- MLP head ----
    gemm_mma<<<nsm, 512, GSM_TOTAL>>>(p_h, b1, p_t1, N_NODES, 1, WH(6), WL(6));
    mlp_tail<<<(N_NODES + 15) / 16, 128>>>(W2, b2, W3, b3, out);
}

// round 16
// speedup vs baseline: 1.0211x; 1.0211x over previous
#include <cuda_runtime.h>
#include <cuda_bf16.h>
#include <math.h>
#include <stdint.h>

#define N_NODES 50000
#define E_EDGES 800000
#define N_ET    (E_EDGES + N_NODES)   // 850000 edges incl. self loops
#define EDIM    101
#define LP      104                   // padded loop_attr pitch
#define HC      128
#define NH      4

// ---- edge mma config: pair-local 16-edge blocks, permuted LDS.64 layout ----
#define NBLK    ((N_ET + 15) / 16)    // 53125
#define NKS     7                     // k-steps of 16 (K padded to 112)
#define PW      72                    // A/B row pitch in words (== 8 mod 32)
#define EEP     132                   // ee row pitch (floats)

// fragment-pair permutation within each 8-word group
#define PERMQ(kq) (((kq) & ~7) | ((((kq) & 3)) << 1) | (((kq) & 7) >> 2))

// edge smem offsets (bytes)
#define SM_SS    0
#define SM_DS    512
#define SM_BHI   1024                 // 128*72*4 = 36864
#define SM_BLO   (SM_BHI + 36864)
#define SM_AHI   (SM_BLO + 36864)
#define SM_ALO   (SM_AHI + 36864)
#define SM_EE    (SM_ALO + 36864)     // 8*16*132*4 = 67584
#define SM_TOTAL (SM_EE + 67584)      // 216064

// gemm smem (single): pitch 68 words
#define GPW      68
#define GSM_BHI  0
#define GSM_BLO  (128*GPW*4)
#define GSM_AHI  (2*128*GPW*4)
#define GSM_ALO  (3*128*GPW*4)
#define GSM_TOTAL (4*128*GPW*4)       // 139264

// dual gemm smem: B1h,B1l,B2h,B2l,Ah,Al
#define DSM_B1H  0
#define DSM_B1L  34816
#define DSM_B2H  69632
#define DSM_B2L  104448
#define DSM_AH   139264
#define DSM_AL   174080
#define DSM_TOTAL 208896

// ------------------------------ scratch ------------------------------------
__device__ int      g_is64;
__device__ int      g_eidx[2 * E_EDGES];
__device__ float    g_loop[(size_t)N_NODES * LP];
__device__ float    g_xl  [(size_t)N_NODES * HC];
__device__ float    g_xr  [(size_t)N_NODES * HC];
__device__ float    g_h   [(size_t)N_NODES * HC];
__device__ float    g_t1  [(size_t)N_NODES * HC];
__device__ float    g_den [(size_t)N_NODES * NH];
__device__ float    g_agg [(size_t)N_NODES * HC];
// preconverted weights: 7 slots (c1_Wl, c1_Wr, c1_We, c2_Wl, c2_Wr, c2_We, W1)
__device__ uint32_t g_wh[7][128 * 64];
__device__ uint32_t g_wl[7][128 * 64];
// CSR scratch
__device__ int      g_deg [N_NODES];
__device__ int      g_off [N_NODES + 1];
__device__ int      g_pos [N_NODES];
__device__ int      g_eid [E_EDGES];
__device__ int      g_bsum[64];
__device__ int      g_bpre[64];

// ------------------------------ helpers ------------------------------------
__device__ __forceinline__ void redAdd4(float* p, float4 v) {
    asm volatile("red.global.add.v4.f32 [%0], {%1,%2,%3,%4};"
                 :: "l"(p), "f"(v.x), "f"(v.y), "f"(v.z), "f"(v.w) : "memory");
}

// truncation-based bf16 hi/lo split of a float pair (residual 2^-16 after 3-term)
__device__ __forceinline__ void split_trunc(float v0, float v1,
                                            uint32_t& hi, uint32_t& lo) {
    uint32_t u0 = __float_as_uint(v0), u1 = __float_as_uint(v1);
    hi = __byte_perm(u0, u1, 0x7632);
    float r0 = v0 - __uint_as_float(u0 & 0xFFFF0000u);
    float r1 = v1 - __uint_as_float(u1 & 0xFFFF0000u);
    lo = __byte_perm(__float_as_uint(r0), __float_as_uint(r1), 0x7632);
}

// HMMA m16n8k16 bf16 (baseline PTX, sm_80+)
__device__ __forceinline__ void mma_bf16(float* d,
                                         uint32_t a0, uint32_t a1, uint32_t a2, uint32_t a3,
                                         uint32_t b0, uint32_t b1) {
    asm volatile("mma.sync.aligned.m16n8k16.row.col.f32.bf16.bf16.f32 "
                 "{%0,%1,%2,%3}, {%4,%5,%6,%7}, {%8,%9}, {%0,%1,%2,%3};"
                 : "+f"(d[0]), "+f"(d[1]), "+f"(d[2]), "+f"(d[3])
                 : "r"(a0), "r"(a1), "r"(a2), "r"(a3), "r"(b0), "r"(b1));
}

#define PAIR_BAR(pair) asm volatile("bar.sync %0, %1;" :: "r"((pair) + 1), "r"(64) : "memory")

// ---------- index dtype detect + g_deg zeroing (wide grid) ------------------
__global__ void detect_idx(const void* ei) {
    int i = blockIdx.x * blockDim.x + threadIdx.x;
    if (i < N_NODES) g_deg[i] = 0;
    if (i == 0) {
        const int* p = (const int*)ei;
        int all0 = 1;
        for (int j = 1; j < 64; j += 2) if (p[j] != 0) all0 = 0;
        g_is64 = all0;
    }
}

// convert indices AND count degrees (deg for dst half)
__global__ void conv_idx(const void* ei) {
    int i = blockIdx.x * blockDim.x + threadIdx.x;
    if (i >= 2 * E_EDGES) return;
    int v;
    if (g_is64) v = (int)((const long long*)ei)[i];
    else        v = ((const int*)ei)[i];
    g_eidx[i] = v;
    if (i >= E_EDGES) atomicAdd(&g_deg[v], 1);
}

// ------------------------------ CSR loop-attr mean --------------------------
__global__ void scan_part() {
    __shared__ int red[32];
    int t = threadIdx.x;
    int lane = t & 31, wid = t >> 5;
    int n = blockIdx.x * 1024 + t;
    int v = (n < N_NODES) ? g_deg[n] : 0;
#pragma unroll
    for (int off = 16; off > 0; off >>= 1)
        v += __shfl_down_sync(0xffffffffu, v, off);
    if (lane == 0) red[wid] = v;
    __syncthreads();
    if (wid == 0) {
        int s = red[lane];
#pragma unroll
        for (int off = 16; off > 0; off >>= 1)
            s += __shfl_down_sync(0xffffffffu, s, off);
        if (lane == 0) g_bsum[blockIdx.x] = s;
    }
}

__global__ void scan_top(int nblocks) {
    __shared__ int s[64];
    int t = threadIdx.x;
    int v = (t < nblocks) ? g_bsum[t] : 0;
    s[t] = v;
    __syncthreads();
#pragma unroll
    for (int off = 1; off < 64; off <<= 1) {
        int u = (t >= off) ? s[t - off] : 0;
        __syncthreads();
        s[t] += u;
        __syncthreads();
    }
    g_bpre[t] = s[t] - v;
}

__global__ void scan_fin() {
    __shared__ int wsum[32];
    int t = threadIdx.x;
    int lane = t & 31, wid = t >> 5;
    int n = blockIdx.x * 1024 + t;
    int v = (n < N_NODES) ? g_deg[n] : 0;
    int x = v;
#pragma unroll
    for (int off = 1; off < 32; off <<= 1) {
        int u = __shfl_up_sync(0xffffffffu, x, off);
        if (lane >= off) x += u;
    }
    if (lane == 31) wsum[wid] = x;
    __syncthreads();
    if (wid == 0) {
        int y = wsum[lane];
#pragma unroll
        for (int off = 1; off < 32; off <<= 1) {
            int u = __shfl_up_sync(0xffffffffu, y, off);
            if (lane >= off) y += u;
        }
        wsum[lane] = y;
    }
    __syncthreads();
    int bpre = (wid > 0) ? wsum[wid - 1] : 0;
    int excl = x - v + bpre + g_bpre[blockIdx.x];
    if (n < N_NODES) {
        g_off[n] = excl;
        g_pos[n] = excl;
    }
    if (blockIdx.x == 0 && t == 0) g_off[N_NODES] = E_EDGES;
}

__global__ void scatter_eid(const int* __restrict__ dst) {
    int e = blockIdx.x * blockDim.x + threadIdx.x;
    if (e >= E_EDGES) return;
    int p = atomicAdd(&g_pos[dst[e]], 1);
    g_eid[p] = e;
}

// warp per node, unrolled x2 (two row fetches in flight)
__global__ void loop_mean(const float* __restrict__ ea) {
    int n = blockIdx.x * 8 + (threadIdx.x >> 5);
    if (n >= N_NODES) return;
    int lane = threadIdx.x & 31;
    int c0 = lane << 2;
    int o0 = g_off[n], o1 = g_off[n + 1];
    float a0 = 0.f, a1 = 0.f, a2 = 0.f, a3 = 0.f;
    float b0 = 0.f, b1 = 0.f, b2 = 0.f, b3 = 0.f;
    int j = o0;
    for (; j + 1 < o1; j += 2) {
        const float* p0 = ea + (size_t)g_eid[j]     * EDIM;
        const float* p1 = ea + (size_t)g_eid[j + 1] * EDIM;
        if (c0 < EDIM)     { a0 += p0[c0];     b0 += p1[c0]; }
        if (c0 + 1 < EDIM) { a1 += p0[c0 + 1]; b1 += p1[c0 + 1]; }
        if (c0 + 2 < EDIM) { a2 += p0[c0 + 2]; b2 += p1[c0 + 2]; }
        if (c0 + 3 < EDIM) { a3 += p0[c0 + 3]; b3 += p1[c0 + 3]; }
    }
    if (j < o1) {
        const float* p0 = ea + (size_t)g_eid[j] * EDIM;
        if (c0 < EDIM)     a0 += p0[c0];
        if (c0 + 1 < EDIM) a1 += p0[c0 + 1];
        if (c0 + 2 < EDIM) a2 += p0[c0 + 2];
        if (c0 + 3 < EDIM) a3 += p0[c0 + 3];
    }
    float inv = 1.f / (float)max(o1 - o0, 1);
    float* out = g_loop + (size_t)n * LP;
    if (c0 < EDIM)     out[c0]     = (a0 + b0) * inv;
    if (c0 + 1 < EDIM) out[c0 + 1] = (a1 + b1) * inv;
    if (c0 + 2 < EDIM) out[c0 + 2] = (a2 + b2) * inv;
    if (c0 + 3 < EDIM) out[c0 + 3] = (a3 + b3) * inv;
}

// ---- batched weight preconversion: all 7 weights -> hi/lo slots -----------
__global__ void convW7(const float* W0, const float* W1_, const float* W2_,
                       const float* W3_, const float* W4_, const float* W5_,
                       const float* W6_) {
    int gid = blockIdx.x * 256 + threadIdx.x;
    int slot = gid >> 13;              // 8192 entries per slot
    int idx = gid & 8191;
    if (slot >= 7) return;
    const float* W;
    int kmax;
    switch (slot) {
        case 0: W = W0;  kmax = 128;  break;
        case 1: W = W1_; kmax = 128;  break;
        case 2: W = W2_; kmax = EDIM; break;
        case 3: W = W3_; kmax = 128;  break;
        case 4: W = W4_; kmax = 128;  break;
        case 5: W = W5_; kmax = EDIM; break;
        default: W = W6_; kmax = 128; break;
    }
    int c = idx >> 6, kq = idx & 63;
    int k = kq * 2;
    float v0 = (k     < kmax) ? W[(size_t)k * 128 + c]       : 0.f;
    float v1 = (k + 1 < kmax) ? W[(size_t)(k + 1) * 128 + c] : 0.f;
    uint32_t h, l;
    split_trunc(v0, v1, h, l);
    g_wh[slot][idx] = h;
    g_wl[slot][idx] = l;
}

// ------------- persistent HMMA node GEMM (single W) -------------------------
__global__ __launch_bounds__(512, 1)
void gemm_mma(const float* __restrict__ A, const float* __restrict__ bias,
              float* __restrict__ C, int M, int relu,
              const uint32_t* __restrict__ wh, const uint32_t* __restrict__ wl) {
    extern __shared__ __align__(16) char sm[];
    uint32_t* Bh = (uint32_t*)(sm + GSM_BHI);
    uint32_t* Bl = (uint32_t*)(sm + GSM_BLO);
    uint32_t* Ah = (uint32_t*)(sm + GSM_AHI);
    uint32_t* Al = (uint32_t*)(sm + GSM_ALO);

    int t = threadIdx.x;
    int lane = t & 31;
    int w = t >> 5;
    int mb = w >> 1, half = w & 1;
    int r0 = lane >> 2, kp = lane & 3;

#pragma unroll
    for (int i = 0; i < 16; i++) {
        int idx = t + i * 512;
        int c = idx >> 6, kq = idx & 63;
        Bh[c * GPW + kq] = wh[idx];
        Bl[c * GPW + kq] = wl[idx];
    }

    int r = t >> 2;
    int kq0 = (t & 3) << 4;
    int cb = (half << 6) + (kp << 1);

    for (int m0 = blockIdx.x << 7; m0 < M; m0 += gridDim.x << 7) {
        __syncthreads();   // prev tile MMA reads of A done (covers B on iter 0)
        {
            int m = m0 + r;
            const float* ap = A + (size_t)m * 128 + (kq0 << 1);
            uint32_t* ah = Ah + r * GPW + kq0;
            uint32_t* al = Al + r * GPW + kq0;
            bool ok = (m < M);
#pragma unroll
            for (int i = 0; i < 16; i++) {
                float v0 = ok ? ap[2*i]     : 0.f;
                float v1 = ok ? ap[2*i + 1] : 0.f;
                uint32_t h, l;
                split_trunc(v0, v1, h, l);
                ah[i] = h;
                al[i] = l;
            }
        }
        __syncthreads();

        float acc[8][4];
#pragma unroll
        for (int nb = 0; nb < 8; nb++)
#pragma unroll
            for (int j = 0; j < 4; j++) acc[nb][j] = 0.f;

        const uint32_t* Awh = Ah + (mb << 4) * GPW;
        const uint32_t* Awl = Al + (mb << 4) * GPW;
        const uint32_t* Bwh = Bh + (half << 6) * GPW;
        const uint32_t* Bwl = Bl + (half << 6) * GPW;

#pragma unroll
        for (int ks = 0; ks < 8; ks++) {
            int abase = r0 * GPW + ks * 8 + kp;
            uint32_t ah0 = Awh[abase],     ah1 = Awh[abase + 8 * GPW];
            uint32_t ah2 = Awh[abase + 4], ah3 = Awh[abase + 8 * GPW + 4];
            uint32_t al0 = Awl[abase],     al1 = Awl[abase + 8 * GPW];
            uint32_t al2 = Awl[abase + 4], al3 = Awl[abase + 8 * GPW + 4];
#pragma unroll
            for (int nb = 0; nb < 8; nb++) {
                int bbase = ((nb << 3) + r0) * GPW + ks * 8 + kp;
                uint32_t bh0 = Bwh[bbase], bh1 = Bwh[bbase + 4];
                uint32_t bl0 = Bwl[bbase], bl1 = Bwl[bbase + 4];
                mma_bf16(acc[nb], ah0, ah1, ah2, ah3, bh0, bh1);
                mma_bf16(acc[nb], ah0, ah1, ah2, ah3, bl0, bl1);
                mma_bf16(acc[nb], al0, al1, al2, al3, bh0, bh1);
            }
        }

        int mA = m0 + (mb << 4) + r0;
        int mB = mA + 8;
#pragma unroll
        for (int nb = 0; nb < 8; nb++) {
            int c0 = cb + (nb << 3);
            float2 bv = *(const float2*)(bias + c0);
            float o0 = acc[nb][0] + bv.x, o1 = acc[nb][1] + bv.y;
            float o2 = acc[nb][2] + bv.x, o3 = acc[nb][3] + bv.y;
            if (relu) {
                o0 = fmaxf(o0, 0.f); o1 = fmaxf(o1, 0.f);
                o2 = fmaxf(o2, 0.f); o3 = fmaxf(o3, 0.f);
            }
            if (mA < M) *(float2*)(C + (size_t)mA * 128 + c0) = make_float2(o0, o1);
            if (mB < M) *(float2*)(C + (size_t)mB * 128 + c0) = make_float2(o2, o3);
        }
    }
}

// ------------- persistent dual HMMA node GEMM: C1 = A@W1+b1, C2 = A@W2+b2 ---
__global__ __launch_bounds__(512, 1)
void gemm_dual(const float* __restrict__ A,
               const float* __restrict__ b1, const float* __restrict__ b2,
               float* __restrict__ C1, float* __restrict__ C2, int M,
               const uint32_t* __restrict__ w1h, const uint32_t* __restrict__ w1l,
               const uint32_t* __restrict__ w2h, const uint32_t* __restrict__ w2l) {
    extern __shared__ __align__(16) char sm[];
    uint32_t* B1h = (uint32_t*)(sm + DSM_B1H);
    uint32_t* B1l = (uint32_t*)(sm + DSM_B1L);
    uint32_t* B2h = (uint32_t*)(sm + DSM_B2H);
    uint32_t* B2l = (uint32_t*)(sm + DSM_B2L);
    uint32_t* Ah  = (uint32_t*)(sm + DSM_AH);
    uint32_t* Al  = (uint32_t*)(sm + DSM_AL);

    int t = threadIdx.x;
    int lane = t & 31;
    int w = t >> 5;
    int mb = w >> 1, half = w & 1;
    int r0 = lane >> 2, kp = lane & 3;

#pragma unroll
    for (int i = 0; i < 16; i++) {
        int idx = t + i * 512;
        int c = idx >> 6, kq = idx & 63;
        B1h[c * GPW + kq] = w1h[idx];
        B1l[c * GPW + kq] = w1l[idx];
        B2h[c * GPW + kq] = w2h[idx];
        B2l[c * GPW + kq] = w2l[idx];
    }

    int r = t >> 2;
    int kq0 = (t & 3) << 4;
    int cb = (half << 6) + (kp << 1);

    for (int m0 = blockIdx.x << 7; m0 < M; m0 += gridDim.x << 7) {
        __syncthreads();
        {
            int m = m0 + r;
            const float* ap = A + (size_t)m * 128 + (kq0 << 1);
            uint32_t* ah = Ah + r * GPW + kq0;
            uint32_t* al = Al + r * GPW + kq0;
            bool ok = (m < M);
#pragma unroll
            for (int i = 0; i < 16; i++) {
                float v0 = ok ? ap[2*i]     : 0.f;
                float v1 = ok ? ap[2*i + 1] : 0.f;
                uint32_t h, l;
                split_trunc(v0, v1, h, l);
                ah[i] = h;
                al[i] = l;
            }
        }
        __syncthreads();

        const uint32_t* Awh = Ah + (mb << 4) * GPW;
        const uint32_t* Awl = Al + (mb << 4) * GPW;
        int mA = m0 + (mb << 4) + r0;
        int mB = mA + 8;

#pragma unroll
        for (int pass = 0; pass < 2; pass++) {
            const uint32_t* Bwh = (pass ? B2h : B1h) + (half << 6) * GPW;
            const uint32_t* Bwl = (pass ? B2l : B1l) + (half << 6) * GPW;
            const float* bias = pass ? b2 : b1;
            float* C = pass ? C2 : C1;

            float acc[8][4];
#pragma unroll
            for (int nb = 0; nb < 8; nb++)
#pragma unroll
                for (int j = 0; j < 4; j++) acc[nb][j] = 0.f;

#pragma unroll
            for (int ks = 0; ks < 8; ks++) {
                int abase = r0 * GPW + ks * 8 + kp;
                uint32_t ah0 = Awh[abase],     ah1 = Awh[abase + 8 * GPW];
                uint32_t ah2 = Awh[abase + 4], ah3 = Awh[abase + 8 * GPW + 4];
                uint32_t al0 = Awl[abase],     al1 = Awl[abase + 8 * GPW];
                uint32_t al2 = Awl[abase + 4], al3 = Awl[abase + 8 * GPW + 4];
#pragma unroll
                for (int nb = 0; nb < 8; nb++) {
                    int bbase = ((nb << 3) + r0) * GPW + ks * 8 + kp;
                    uint32_t bh0 = Bwh[bbase], bh1 = Bwh[bbase + 4];
                    uint32_t bl0 = Bwl[bbase], bl1 = Bwl[bbase + 4];
                    mma_bf16(acc[nb], ah0, ah1, ah2, ah3, bh0, bh1);
                    mma_bf16(acc[nb], ah0, ah1, ah2, ah3, bl0, bl1);
                    mma_bf16(acc[nb], al0, al1, al2, al3, bh0, bh1);
                }
            }

#pragma unroll
            for (int nb = 0; nb < 8; nb++) {
                int c0 = cb + (nb << 3);
                float2 bv = *(const float2*)(bias + c0);
                float o0 = acc[nb][0] + bv.x, o1 = acc[nb][1] + bv.y;
                float o2 = acc[nb][2] + bv.x, o3 = acc[nb][3] + bv.y;
                if (mA < M) *(float2*)(C + (size_t)mA * 128 + c0) = make_float2(o0, o1);
                if (mB < M) *(float2*)(C + (size_t)mB * 128 + c0) = make_float2(o2, o3);
            }
        }
    }
}

// ==== HMMA fused edge kernel: pair-local pipelines, LDS.64 permuted layout ==
__device__ __forceinline__ void prefetch_attrs(size_t e, int kbase, float* pf,
                                               const float* __restrict__ eattr) {
    bool ok = (e < (size_t)N_ET);
    const float* bp = (e < E_EDGES) ? (eattr + e * EDIM)
                    : (g_loop + (ok ? (e - E_EDGES) : 0) * (size_t)LP);
#pragma unroll
    for (int i = 0; i < 28; i++) {
        int k = kbase + i;
        pf[i] = (ok && k < EDIM) ? bp[k] : 0.f;
    }
}

__global__ __launch_bounds__(512, 1)
void edge_mma(const int* __restrict__ src, const int* __restrict__ dst,
              const float* __restrict__ eattr, const float* __restrict__ att,
              const uint32_t* __restrict__ wh, const uint32_t* __restrict__ wl) {
    extern __shared__ __align__(16) char sm[];
    int*      ssS = (int*)(sm + SM_SS);
    int*      dsS = (int*)(sm + SM_DS);
    uint32_t* Bhi = (uint32_t*)(sm + SM_BHI);
    uint32_t* Blo = (uint32_t*)(sm + SM_BLO);
    uint32_t* Ahi = (uint32_t*)(sm + SM_AHI);
    uint32_t* Alo = (uint32_t*)(sm + SM_ALO);
    float*    ee  = (float*)(sm + SM_EE);

    int t = threadIdx.x;
    int lane = t & 31;
    int w = t >> 5;
    int pair = w >> 1, half = w & 1;
    int r0 = lane >> 2, kp = lane & 3;
    int head = lane >> 3;
    int u = t & 63;

    // copy preconverted We into permuted smem (kq -> PERMQ(kq), pitch 72)
    for (int i = t; i < 128 * 56; i += 512) {
        int c = i / 56, kq = i - c * 56;
        int pq = PERMQ(kq);
        Bhi[c * PW + pq] = wh[(c << 6) + kq];
        Blo[c * PW + pq] = wl[(c << 6) + kq];
    }
    float4 av = *(const float4*)(att + (lane << 2));
    __syncthreads();

    uint32_t* pAh = Ahi + pair * (16 * PW);
    uint32_t* pAl = Alo + pair * (16 * PW);
    float*    pee = ee  + pair * (16 * EEP);
    float2*   pee2 = (float2*)pee;
    int*      pss = ssS + (pair << 4);
    int*      pds = dsS + (pair << 4);

    const uint32_t* Bwh = Bhi + (half << 6) * PW;
    const uint32_t* Bwl = Blo + (half << 6) * PW;

    int e_st = u >> 2;
    int kq0 = (u & 3) * 14;
    int kbase = kq0 * 2;
    int stride = gridDim.x * 8;
    int blk0 = blockIdx.x * 8 + pair;

    float pf[28];
    prefetch_attrs((size_t)blk0 * 16 + e_st, kbase, pf, eattr);

    for (int blk = blk0; blk < NBLK; blk += stride) {
        size_t e0 = (size_t)blk * 16;

        if (u < 16) {
            size_t e = e0 + u;
            int s = 0, d = 0;
            if (e < (size_t)N_ET) {
                if (e < E_EDGES) { s = src[e]; d = dst[e]; }
                else             { s = d = (int)(e - E_EDGES); }
            }
            pss[u] = s; pds[u] = d;
        }
        {
            uint32_t* ah = pAh + e_st * PW;
            uint32_t* al = pAl + e_st * PW;
#pragma unroll
            for (int i = 0; i < 14; i++) {
                int kq = kq0 + i;
                int pq = PERMQ(kq);
                uint32_t h, l;
                split_trunc(pf[2*i], pf[2*i + 1], h, l);
                ah[pq] = h;
                al[pq] = l;
            }
        }
        if (blk + stride < NBLK)
            prefetch_attrs((size_t)(blk + stride) * 16 + e_st, kbase, pf, eattr);

        PAIR_BAR(pair);

        float acc[8][4];
#pragma unroll
        for (int nb = 0; nb < 8; nb++)
#pragma unroll
            for (int j = 0; j < 4; j++) acc[nb][j] = 0.f;

#pragma unroll
        for (int ks = 0; ks < NKS; ks++) {
            int ab = r0 * PW + ks * 8 + (kp << 1);
            uint2 aH0 = *(const uint2*)(pAh + ab);
            uint2 aH1 = *(const uint2*)(pAh + ab + 8 * PW);
            uint2 aL0 = *(const uint2*)(pAl + ab);
            uint2 aL1 = *(const uint2*)(pAl + ab + 8 * PW);
#pragma unroll
            for (int nb = 0; nb < 8; nb++) {
                int bb = ((nb << 3) + r0) * PW + ks * 8 + (kp << 1);
                uint2 bH = *(const uint2*)(Bwh + bb);
                uint2 bL = *(const uint2*)(Bwl + bb);
                mma_bf16(acc[nb], aH0.x, aH1.x, aH0.y, aH1.y, bH.x, bH.y);
                mma_bf16(acc[nb], aH0.x, aH1.x, aH0.y, aH1.y, bL.x, bL.y);
                mma_bf16(acc[nb], aL0.x, aL1.x, aL0.y, aL1.y, bH.x, bH.y);
            }
        }

#pragma unroll
        for (int nb = 0; nb < 8; nb++) {
            int col2 = (half << 5) + (nb << 2) + kp;
            pee2[r0 * (EEP / 2) + col2]       = make_float2(acc[nb][0], acc[nb][1]);
            pee2[(r0 + 8) * (EEP / 2) + col2] = make_float2(acc[nb][2], acc[nb][3]);
        }

        int sreg[8], dreg[8];
        bool vv[8];
#pragma unroll
        for (int i = 0; i < 8; i++) {
            int el = (half << 3) + i;
            size_t e = e0 + el;
            vv[i] = (e < (size_t)N_ET);
            sreg[i] = vv[i] ? pss[el] : 0;
            dreg[i] = vv[i] ? pds[el] : 0;
        }

        PAIR_BAR(pair);

#pragma unroll
        for (int g = 0; g < 2; g++) {
            float4 xlv[4], xrv[4];
#pragma unroll
            for (int i = 0; i < 4; i++) {
                int j = (g << 2) + i;
                xlv[i] = *(const float4*)(g_xl + (size_t)sreg[j] * HC + (lane << 2));
                xrv[i] = *(const float4*)(g_xr + (size_t)dreg[j] * HC + (lane << 2));
            }
#pragma unroll
            for (int i = 0; i < 4; i++) {
                int j = (g << 2) + i;
                int el = (half << 3) + j;
                float4 eev = *(const float4*)(pee + el * EEP + (lane << 2));
                float z0 = eev.x + xlv[i].x + xrv[i].x;
                float z1 = eev.y + xlv[i].y + xrv[i].y;
                float z2 = eev.z + xlv[i].z + xrv[i].z;
                float z3 = eev.w + xlv[i].w + xrv[i].w;
                z0 = (z0 > 0.f) ? z0 : 0.2f * z0;
                z1 = (z1 > 0.f) ? z1 : 0.2f * z1;
                z2 = (z2 > 0.f) ? z2 : 0.2f * z2;
                z3 = (z3 > 0.f) ? z3 : 0.2f * z3;
                float part = z0 * av.x + z1 * av.y + z2 * av.z + z3 * av.w;
                part += __shfl_xor_sync(0xffffffffu, part, 1);
                part += __shfl_xor_sync(0xffffffffu, part, 2);
                part += __shfl_xor_sync(0xffffffffu, part, 4);
                float ex = __expf(part);
                if (vv[j]) {
                    if ((lane & 7) == 0)
                        atomicAdd(&g_den[(size_t)dreg[j] * NH + head], ex);
                    redAdd4(g_agg + (size_t)dreg[j] * HC + (lane << 2),
                            make_float4(ex * xlv[i].x, ex * xlv[i].y,
                                        ex * xlv[i].z, ex * xlv[i].w));
                }
            }
        }
    }
}

// ---- h = relu(agg/(den+eps) + bias); then zero agg/den for next layer/call -
__global__ void node_finalize(const float* __restrict__ bias, float* __restrict__ out) {
    size_t i = (size_t)blockIdx.x * blockDim.x + threadIdx.x;   // exact grid
    int n = (int)(i >> 7), c = (int)(i & 127);
    float den = g_den[(size_t)n * NH + (c >> 5)];
    float agg = g_agg[i];
    __syncthreads();   // all reads of den in this block done before zeroing
    float v = agg / (den + 1e-16f) + bias[c];
    out[i] = fmaxf(v, 0.f);
    g_agg[i] = 0.f;
    if ((c & 31) == 0) g_den[(size_t)n * NH + (c >> 5)] = 0.f;
}

// --------------------- MLP tail: relu(t1@W2+b2) @ W3 + b3 ------------------
__global__ void mlp_tail(const float* __restrict__ W2, const float* __restrict__ b2,
                         const float* __restrict__ W3, const float* __restrict__ b3,
                         float* __restrict__ out) {
    __shared__ float W2s[128 * 64];
    __shared__ float t1s[16 * 132];
    __shared__ float W3s[64];
    int t = threadIdx.x;
    int n0 = blockIdx.x * 16;
    for (int i = t; i < 128 * 64 / 4; i += 128)
        ((float4*)W2s)[i] = ((const float4*)W2)[i];
    if (t < 64) W3s[t] = W3[t];
    for (int i = t; i < 16 * 128; i += 128) {
        int ln = i >> 7, k = i & 127;
        int n = n0 + ln;
        t1s[ln * 132 + k] = (n < N_NODES) ? g_t1[(size_t)n * 128 + k] : 0.f;
    }
    __syncthreads();
    int ln = t >> 3, jg = t & 7;
    float acc[8] = {0.f, 0.f, 0.f, 0.f, 0.f, 0.f, 0.f, 0.f};
#pragma unroll 4
    for (int k = 0; k < 128; k++) {
        float a = t1s[ln * 132 + k];
        float4 w0 = *(const float4*)(W2s + k * 64 + jg * 8);
        float4 w1 = *(const float4*)(W2s + k * 64 + jg * 8 + 4);
        acc[0] += a * w0.x; acc[1] += a * w0.y; acc[2] += a * w0.z; acc[3] += a * w0.w;
        acc[4] += a * w1.x; acc[5] += a * w1.y; acc[6] += a * w1.z; acc[7] += a * w1.w;
    }
    float part = 0.f;
#pragma unroll
    for (int j = 0; j < 8; j++) {
        float t2 = fmaxf(acc[j] + b2[jg * 8 + j], 0.f);
        part += t2 * W3s[jg * 8 + j];
    }
    part += __shfl_down_sync(0xffffffffu, part, 4, 8);
    part += __shfl_down_sync(0xffffffffu, part, 2, 8);
    part += __shfl_down_sync(0xffffffffu, part, 1, 8);
    int n = n0 + ln;
    if (jg == 0 && n < N_NODES) out[n] = part + b3[0];
}

// ------------------------------ launch -------------------------------------
extern "C" void kernel_launch(void* const* d_in, const int* in_sizes, int n_in,
                              void* d_out, int out_size) {
    const float* x       = (const float*)d_in[0];
    const void*  ei_raw  = d_in[1];
    const float* ea      = (const float*)d_in[2];
    const float* c1_Wl   = (const float*)d_in[3];
    const float* c1_bl   = (const float*)d_in[4];
    const float* c1_Wr   = (const float*)d_in[5];
    const float* c1_br   = (const float*)d_in[6];
    const float* c1_We   = (const float*)d_in[7];
    const float* c1_att  = (const float*)d_in[8];
    const float* c1_bias = (const float*)d_in[9];
    const float* c2_Wl   = (const float*)d_in[10];
    const float* c2_bl   = (const float*)d_in[11];
    const float* c2_Wr   = (const float*)d_in[12];
    const float* c2_br   = (const float*)d_in[13];
    const float* c2_We   = (const float*)d_in[14];
    const float* c2_att  = (const float*)d_in[15];
    const float* c2_bias = (const float*)d_in[16];
    const float* W1      = (const float*)d_in[17];
    const float* b1      = (const float*)d_in[18];
    const float* W2      = (const float*)d_in[19];
    const float* b2      = (const float*)d_in[20];
    const float* W3      = (const float*)d_in[21];
    const float* b3      = (const float*)d_in[22];
    float* out = (float*)d_out;

    float *p_xl, *p_xr, *p_h, *p_t1;
    int *p_eidx;
    uint32_t *p_wh, *p_wl;
    cudaGetSymbolAddress((void**)&p_xl, g_xl);
    cudaGetSymbolAddress((void**)&p_xr, g_xr);
    cudaGetSymbolAddress((void**)&p_h, g_h);
    cudaGetSymbolAddress((void**)&p_t1, g_t1);
    cudaGetSymbolAddress((void**)&p_eidx, g_eidx);
    cudaGetSymbolAddress((void**)&p_wh, g_wh);
    cudaGetSymbolAddress((void**)&p_wl, g_wl);
    const int* src = p_eidx;
    const int* dst = p_eidx + E_EDGES;
#define WH(s) (p_wh + (s) * 8192)
#define WL(s) (p_wl + (s) * 8192)

    cudaFuncSetAttribute(edge_mma,
                         cudaFuncAttributeMaxDynamicSharedMemorySize, SM_TOTAL);
    cudaFuncSetAttribute(gemm_mma,
                         cudaFuncAttributeMaxDynamicSharedMemorySize, GSM_TOTAL);
    cudaFuncSetAttribute(gemm_dual,
                         cudaFuncAttributeMaxDynamicSharedMemorySize, DSM_TOTAL);

    int nsm = 148;
    cudaDeviceGetAttribute(&nsm, cudaDevAttrMultiProcessorCount, 0);

    const int T = 256;
    int nhc_blocks = (int)(((size_t)N_NODES * HC) / T);  // 25000 exact
    int scan_blocks = (N_NODES + 1023) / 1024;           // 49
    int cw7_blocks = (7 * 8192 + 255) / 256;             // 224

    // detect dtype + zero g_deg (wide grid)
    detect_idx<<<(N_NODES + T - 1) / T, T>>>(ei_raw);
    // convert indices + count degrees in one pass
    conv_idx<<<(2 * E_EDGES + T - 1) / T, T>>>(ei_raw);

    // all weight conversions up front (one launch)
    convW7<<<cw7_blocks, 256>>>(c1_Wl, c1_Wr, c1_We, c2_Wl, c2_Wr, c2_We, W1);

    // CSR loop-attr mean
    scan_part<<<scan_blocks, 1024>>>();
    scan_top<<<1, 64>>>(scan_blocks);
    scan_fin<<<scan_blocks, 1024>>>();
    scatter_eid<<<(E_EDGES + T - 1) / T, T>>>(dst);
    loop_mean<<<(N_NODES + 7) / 8, T>>>(ea);

    // ---- layer 1 ----
    gemm_dual<<<nsm, 512, DSM_TOTAL>>>(x, c1_bl, c1_br, p_xl, p_xr, N_NODES,
                                       WH(0), WL(0), WH(1), WL(1));
    edge_mma<<<nsm, 512, SM_TOTAL>>>(src, dst, ea, c1_att, WH(2), WL(2));
    node_finalize<<<nhc_blocks, T>>>(c1_bias, p_h);

    // ---- layer 2 ----
    gemm_dual<<<nsm, 512, DSM_TOTAL>>>(p_h, c2_bl, c2_br, p_xl, p_xr, N_NODES,
                                       WH(3), WL(3), WH(4), WL(4));
    edge_mma<<<nsm, 512, SM_TOTAL>>>(src, dst, ea, c2_att, WH(5), WL(5));
    node_finalize<<<nhc_blocks, T>>>(c2_bias, p_h);

    // ---- MLP head ----
    gemm_mma<<<nsm, 512, GSM_TOTAL>>>(p_h, b1, p_t1, N_NODES, 1, WH(6), WL(6));
    mlp_tail<<<(N_NODES + 15) / 16, 128>>>(W2, b2, W3, b3, out);
}